// round 6
// baseline (speedup 1.0000x reference)
#include <cuda_runtime.h>

#define N_STATE 131072
#define H 128
#define NB 512                     // blocks — must all be co-resident (148 SMs x 4)
#define TPB 256
#define CHUNK (N_STATE / NB)       // 256 columns per block

// Scratch (device globals — no allocation allowed)
__device__ float g_ypart[NB * H];
__device__ float g_r[H];
__device__ unsigned long long g_tickets;   // monotonic barrier counter (zero-init)

// Monotonic-ticket grid barrier: no reset needed across graph replays.
// Every block calls it the same number of times; round k completes when
// the global ticket count reaches k*NB.
__device__ __forceinline__ void grid_barrier()
{
    __threadfence();
    __syncthreads();
    if (threadIdx.x == 0) {
        unsigned long long t = atomicAdd(&g_tickets, 1ULL) + 1ULL;
        unsigned long long target = ((t + NB - 1ULL) / NB) * NB;
        while (atomicAdd(&g_tickets, 0ULL) < target)
            __nanosleep(64);
        __threadfence();
    }
    __syncthreads();
}

__global__ __launch_bounds__(TPB, 4)
void k_fused(const float* __restrict__ state,
             const float* __restrict__ xmax,
             const float* __restrict__ xmin,
             const float* __restrict__ W0,
             const float* __restrict__ b0,
             const float* __restrict__ W1, const float* __restrict__ b1,
             const float* __restrict__ W2, const float* __restrict__ b2,
             const float* __restrict__ W3, const float* __restrict__ b3,
             const float* __restrict__ Wout, const float* __restrict__ bout,
             float* __restrict__ out)
{
    __shared__ float xs[CHUNK];          // normalized x for this block's columns
    __shared__ float sc[CHUNK];          // 2/(mx-mn) for this block's columns
    __shared__ float sh[H];              // core: activations; phase3: r
    __shared__ float d0[H], d1[H], d2[H], tvec[H];
    __shared__ float red[8];

    const int tid = threadIdx.x;
    const int b = blockIdx.x;
    const int n0 = b * CHUNK;

    // ---- normalize this block's column chunk (state/xmax/xmin read once, ever)
    {
        float s  = state[n0 + tid];
        float mx = xmax[n0 + tid];
        float mn = xmin[n0 + tid];
        float inv = 1.0f / (mx - mn);
        xs[tid] = (2.0f * s - mx - mn) * inv;
        sc[tid] = 2.0f * inv;
    }
    __syncthreads();

    // ---- phase 1: y partials over this chunk for all 128 rows
    // warp w handles rows w*16 .. w*16+15; 2 float4 loads per row per lane.
    {
        const int warp = tid >> 5, lane = tid & 31;
        float4 x0 = ((const float4*)xs)[lane];
        float4 x1 = ((const float4*)xs)[32 + lane];
        #pragma unroll 4
        for (int rr = 0; rr < H / 8; rr++) {
            const int j = warp * (H / 8) + rr;
            const float4* __restrict__ w4 =
                (const float4*)(W0 + (size_t)j * N_STATE + n0);
            float4 a = w4[lane];
            float4 c = w4[32 + lane];
            float p = a.x * x0.x + a.y * x0.y + a.z * x0.z + a.w * x0.w
                    + c.x * x1.x + c.y * x1.y + c.z * x1.z + c.w * x1.w;
            #pragma unroll
            for (int o = 16; o > 0; o >>= 1)
                p += __shfl_down_sync(0xffffffffu, p, o);
            if (lane == 0) g_ypart[(size_t)b * H + j] = p;
        }
    }

    grid_barrier();

    // ---- phase 2: tiny serial core on block 0 (others wait at next barrier)
    if (b == 0) {
        const int j = tid;
        float Vnew = 0.0f;

        if (j < H) {
            float y = 0.0f;
            #pragma unroll 8
            for (int s = 0; s < NB; s++) y += g_ypart[(size_t)s * H + j];
            Vnew = tanhf(y + b0[j]);
            d0[j] = 1.0f - Vnew * Vnew;
            sh[j] = Vnew;
        }
        __syncthreads();

        if (j < H) {                               // layer 0: W1 + tanh
            float a = b1[j];
            #pragma unroll 8
            for (int k = 0; k < H; k++) a += W1[j * H + k] * sh[k];
            Vnew = tanhf(a);
            d1[j] = 1.0f - Vnew * Vnew;
        }
        __syncthreads();
        if (j < H) sh[j] = Vnew;
        __syncthreads();

        if (j < H) {                               // layer 1: W2 + tanh
            float a = b2[j];
            #pragma unroll 8
            for (int k = 0; k < H; k++) a += W2[j * H + k] * sh[k];
            Vnew = tanhf(a);
            d2[j] = 1.0f - Vnew * Vnew;
        }
        __syncthreads();
        if (j < H) sh[j] = Vnew;
        __syncthreads();

        if (j < H) {                               // layer 2: W3 (no act)
            float a = b3[j];
            #pragma unroll 8
            for (int k = 0; k < H; k++) a += W3[j * H + k] * sh[k];
            Vnew = a;
        }
        __syncthreads();
        if (j < H) sh[j] = Vnew;
        __syncthreads();

        if (j < H) {                               // output scalar
            float p = Wout[j] * sh[j];
            #pragma unroll
            for (int o = 16; o > 0; o >>= 1)
                p += __shfl_down_sync(0xffffffffu, p, o);
            if ((j & 31) == 0) red[j >> 5] = p;
        }
        __syncthreads();
        if (j == 0)
            out[0] = red[0] + red[1] + red[2] + red[3] + bout[0];

        // backward collapse: r^T = Wout W3 D2 W2 D1 W1 D0
        if (j < H) tvec[j] = Wout[j];
        __syncthreads();

        if (j < H) {
            float a = 0.0f;
            #pragma unroll 8
            for (int i = 0; i < H; i++) a += tvec[i] * W3[i * H + j];
            Vnew = a * d2[j];
        }
        __syncthreads();
        if (j < H) tvec[j] = Vnew;
        __syncthreads();

        if (j < H) {
            float a = 0.0f;
            #pragma unroll 8
            for (int i = 0; i < H; i++) a += tvec[i] * W2[i * H + j];
            Vnew = a * d1[j];
        }
        __syncthreads();
        if (j < H) tvec[j] = Vnew;
        __syncthreads();

        if (j < H) {
            float a = 0.0f;
            #pragma unroll 8
            for (int i = 0; i < H; i++) a += tvec[i] * W1[i * H + j];
            g_r[j] = a * d0[j];
        }
    }

    grid_barrier();

    // ---- phase 3: JV over the SAME (L2-hot) column chunk
    if (tid < H) sh[tid] = g_r[tid];
    __syncthreads();

    {
        const float* __restrict__ wc = W0 + n0 + tid;
        float acc = 0.0f;
        #pragma unroll 16
        for (int i = 0; i < H; i++)
            acc += sh[i] * wc[(size_t)i * N_STATE];
        out[1 + n0 + tid] = acc * sc[tid];
    }
}

// ---------------------------------------------------------------------------
extern "C" void kernel_launch(void* const* d_in, const int* in_sizes, int n_in,
                              void* d_out, int out_size)
{
    const float* state = (const float*)d_in[0];
    const float* xmax  = (const float*)d_in[1];
    const float* xmin  = (const float*)d_in[2];
    const float* W0    = (const float*)d_in[3];
    const float* b0    = (const float*)d_in[4];
    const float* W1    = (const float*)d_in[5];
    const float* b1    = (const float*)d_in[6];
    const float* W2    = (const float*)d_in[7];
    const float* b2    = (const float*)d_in[8];
    const float* W3    = (const float*)d_in[9];
    const float* b3    = (const float*)d_in[10];
    const float* Wout  = (const float*)d_in[11];
    const float* bout  = (const float*)d_in[12];
    float* out = (float*)d_out;

    k_fused<<<NB, TPB>>>(state, xmax, xmin, W0, b0, W1, b1, W2, b2, W3, b3,
                         Wout, bout, out);
}

// round 8
// speedup vs baseline: 1.1723x; 1.1723x over previous
#include <cuda_runtime.h>

#define N_STATE 131072
#define H 128
#define SEG 32          // n-segments in kernel A
#define RPB 4           // rows per block in kernel A
#define JSPLIT 4        // i-splits in kernel C
#define JROWS (H / JSPLIT)

// Scratch (device globals — no allocation allowed)
__device__ float g_xnorm[N_STATE];
__device__ float g_scale[N_STATE];
__device__ float g_ypart[SEG * H];
__device__ float g_r[H];
__device__ float g_jvpart[JSPLIT * N_STATE];

// ---------------------------------------------------------------------------
// Kernel N: x_norm[n] = (2 s - mx - mn) / (mx - mn);  scale[n] = 2/(mx - mn)
// ---------------------------------------------------------------------------
__global__ __launch_bounds__(256)
void k_norm(const float* __restrict__ state,
            const float* __restrict__ xmax,
            const float* __restrict__ xmin)
{
    const int i = blockIdx.x * blockDim.x + threadIdx.x;   // float4 index
    float4 s  = ((const float4*)state)[i];
    float4 mx = ((const float4*)xmax)[i];
    float4 mn = ((const float4*)xmin)[i];
    float4 inv, xn, sc;
    inv.x = 1.0f / (mx.x - mn.x);
    inv.y = 1.0f / (mx.y - mn.y);
    inv.z = 1.0f / (mx.z - mn.z);
    inv.w = 1.0f / (mx.w - mn.w);
    xn.x = (2.0f * s.x - mx.x - mn.x) * inv.x;
    xn.y = (2.0f * s.y - mx.y - mn.y) * inv.y;
    xn.z = (2.0f * s.z - mx.z - mn.z) * inv.z;
    xn.w = (2.0f * s.w - mx.w - mn.w) * inv.w;
    sc.x = 2.0f * inv.x;  sc.y = 2.0f * inv.y;
    sc.z = 2.0f * inv.z;  sc.w = 2.0f * inv.w;
    ((float4*)g_xnorm)[i] = xn;
    ((float4*)g_scale)[i] = sc;
}

// ---------------------------------------------------------------------------
// Kernel A: partial y. grid (SEG=32, 32 rowgroups) = 1024 blocks x 256 thr.
// Each block: RPB=4 rows x 4096 columns; 4 unrolled its x 5 float4 loads.
// ---------------------------------------------------------------------------
__global__ __launch_bounds__(256)
void k_fwd_matvec(const float* __restrict__ W0)
{
    const int seg = blockIdx.x;
    const int row0 = blockIdx.y * RPB;
    const int chunk4 = (N_STATE / SEG) / 4;                // 1024 float4s

    const float4* __restrict__ xn = (const float4*)g_xnorm + (size_t)seg * chunk4;
    const float4* __restrict__ w0 = (const float4*)(W0 + (size_t)row0 * N_STATE) + (size_t)seg * chunk4;
    const size_t rstride4 = N_STATE / 4;

    float acc[RPB];
    #pragma unroll
    for (int r = 0; r < RPB; r++) acc[r] = 0.0f;

    #pragma unroll
    for (int it = 0; it < (N_STATE / SEG) / 4 / 256; it++) {   // 4 its
        const int i = it * 256 + threadIdx.x;
        float4 x = xn[i];
        #pragma unroll
        for (int r = 0; r < RPB; r++) {
            float4 wv = w0[(size_t)r * rstride4 + i];
            acc[r] += wv.x * x.x + wv.y * x.y + wv.z * x.z + wv.w * x.w;
        }
    }

    __shared__ float red[8][RPB];
    const int lane = threadIdx.x & 31, warp = threadIdx.x >> 5;
    #pragma unroll
    for (int r = 0; r < RPB; r++) {
        float v = acc[r];
        #pragma unroll
        for (int o = 16; o > 0; o >>= 1)
            v += __shfl_down_sync(0xffffffffu, v, o);
        if (lane == 0) red[warp][r] = v;
    }
    __syncthreads();
    if (threadIdx.x < RPB) {
        float v = 0.0f;
        #pragma unroll
        for (int w = 0; w < 8; w++) v += red[w][threadIdx.x];
        g_ypart[seg * H + row0 + threadIdx.x] = v;
    }
}

// ---------------------------------------------------------------------------
// Kernel B: core. 512 threads; each matvec output j computed by 4 threads
// (j = tid>>2, q = tid&3, each sums 32 elements), combined via shfl.
// ---------------------------------------------------------------------------
__global__ __launch_bounds__(512, 1)
void k_core(const float* __restrict__ b0,
            const float* __restrict__ W1, const float* __restrict__ b1,
            const float* __restrict__ W2, const float* __restrict__ b2,
            const float* __restrict__ W3, const float* __restrict__ b3,
            const float* __restrict__ Wout, const float* __restrict__ bout,
            float* __restrict__ out)
{
    __shared__ float v[H];
    __shared__ float tvec[H];
    __shared__ float d0[H], d1[H], d2[H];

    const int tid = threadIdx.x;
    const int j = tid >> 2;        // output index 0..127
    const int q = tid & 3;         // quarter 0..3
    const int k0 = q * 32;

    // y[j] = sum of 32 segment partials; split 8 per q-thread
    {
        float yp = 0.0f;
        #pragma unroll
        for (int s = 0; s < SEG / 4; s++)
            yp += g_ypart[(q * (SEG / 4) + s) * H + j];
        yp += __shfl_down_sync(0xffffffffu, yp, 2);
        yp += __shfl_down_sync(0xffffffffu, yp, 1);
        if (q == 0) {
            float V0 = tanhf(yp + b0[j]);
            d0[j] = 1.0f - V0 * V0;
            v[j] = V0;
        }
    }
    __syncthreads();

    // layer 0: W1 + tanh
    {
        float a = 0.0f;
        #pragma unroll 8
        for (int kk = 0; kk < 32; kk++)
            a += W1[j * H + k0 + kk] * v[k0 + kk];
        a += __shfl_down_sync(0xffffffffu, a, 2);
        a += __shfl_down_sync(0xffffffffu, a, 1);
        __syncthreads();
        if (q == 0) {
            float V1 = tanhf(a + b1[j]);
            d1[j] = 1.0f - V1 * V1;
            v[j] = V1;
        }
    }
    __syncthreads();

    // layer 1: W2 + tanh
    {
        float a = 0.0f;
        #pragma unroll 8
        for (int kk = 0; kk < 32; kk++)
            a += W2[j * H + k0 + kk] * v[k0 + kk];
        a += __shfl_down_sync(0xffffffffu, a, 2);
        a += __shfl_down_sync(0xffffffffu, a, 1);
        __syncthreads();
        if (q == 0) {
            float V2 = tanhf(a + b2[j]);
            d2[j] = 1.0f - V2 * V2;
            v[j] = V2;
        }
    }
    __syncthreads();

    // layer 2: W3 (no activation)
    {
        float a = 0.0f;
        #pragma unroll 8
        for (int kk = 0; kk < 32; kk++)
            a += W3[j * H + k0 + kk] * v[k0 + kk];
        a += __shfl_down_sync(0xffffffffu, a, 2);
        a += __shfl_down_sync(0xffffffffu, a, 1);
        __syncthreads();
        if (q == 0) v[j] = a + b3[j];
    }
    __syncthreads();

    // output scalar: warp 0 only, 4 elements per lane
    if (tid < 32) {
        float p = 0.0f;
        #pragma unroll
        for (int s = 0; s < 4; s++)
            p += Wout[tid + 32 * s] * v[tid + 32 * s];
        #pragma unroll
        for (int o = 16; o > 0; o >>= 1)
            p += __shfl_down_sync(0xffffffffu, p, o);
        if (tid == 0) out[0] = p + bout[0];
    }

    // backward: r^T = Wout W3 D2 W2 D1 W1 D0
    if (tid < H) tvec[tid] = Wout[tid];
    __syncthreads();

    {   // t^T W3, * d2   (column access: lanes j consecutive -> coalesced)
        float a = 0.0f;
        #pragma unroll 8
        for (int kk = 0; kk < 32; kk++)
            a += tvec[k0 + kk] * W3[(k0 + kk) * H + j];
        a += __shfl_down_sync(0xffffffffu, a, 2);
        a += __shfl_down_sync(0xffffffffu, a, 1);
        __syncthreads();
        if (q == 0) tvec[j] = a * d2[j];
    }
    __syncthreads();

    {   // t^T W2, * d1
        float a = 0.0f;
        #pragma unroll 8
        for (int kk = 0; kk < 32; kk++)
            a += tvec[k0 + kk] * W2[(k0 + kk) * H + j];
        a += __shfl_down_sync(0xffffffffu, a, 2);
        a += __shfl_down_sync(0xffffffffu, a, 1);
        __syncthreads();
        if (q == 0) tvec[j] = a * d1[j];
    }
    __syncthreads();

    {   // t^T W1, * d0 -> g_r
        float a = 0.0f;
        #pragma unroll 8
        for (int kk = 0; kk < 32; kk++)
            a += tvec[k0 + kk] * W1[(k0 + kk) * H + j];
        a += __shfl_down_sync(0xffffffffu, a, 2);
        a += __shfl_down_sync(0xffffffffu, a, 1);
        if (q == 0) g_r[j] = a * d0[j];
    }
}

// ---------------------------------------------------------------------------
// Kernel C: partial JV. blockIdx.x = n-chunk (float2), blockIdx.y = i-split.
// grid (256, 4) = 1024 blocks x 256 threads.
// ---------------------------------------------------------------------------
__global__ __launch_bounds__(256)
void k_jv_part(const float* __restrict__ W0)
{
    __shared__ float r[JROWS];
    const int i0 = blockIdx.y * JROWS;
    if (threadIdx.x < JROWS) r[threadIdx.x] = g_r[i0 + threadIdx.x];
    __syncthreads();

    const int n2 = blockIdx.x * blockDim.x + threadIdx.x;   // float2 index
    const float2* __restrict__ w = (const float2*)W0 + (size_t)i0 * (N_STATE / 2);
    const size_t stride2 = N_STATE / 2;

    float ax = 0.0f, ay = 0.0f;
    #pragma unroll 8
    for (int i = 0; i < JROWS; i++) {
        float2 wv = w[(size_t)i * stride2 + n2];
        float ri = r[i];
        ax += ri * wv.x;
        ay += ri * wv.y;
    }

    ((float2*)g_jvpart)[(size_t)blockIdx.y * (N_STATE / 2) + n2] = make_float2(ax, ay);
}

// ---------------------------------------------------------------------------
// Kernel D: combine partials, apply scale, write out[1..N].
// ---------------------------------------------------------------------------
__global__ __launch_bounds__(256)
void k_combine(float* __restrict__ out)
{
    const int i4 = blockIdx.x * blockDim.x + threadIdx.x;   // float4 index
    float4 a = ((const float4*)g_jvpart)[i4];
    float4 b = ((const float4*)(g_jvpart + N_STATE))[i4];
    float4 c = ((const float4*)(g_jvpart + 2 * N_STATE))[i4];
    float4 d = ((const float4*)(g_jvpart + 3 * N_STATE))[i4];
    float4 sc = ((const float4*)g_scale)[i4];
    const int n = i4 * 4;
    out[1 + n + 0] = (a.x + b.x + c.x + d.x) * sc.x;
    out[1 + n + 1] = (a.y + b.y + c.y + d.y) * sc.y;
    out[1 + n + 2] = (a.z + b.z + c.z + d.z) * sc.z;
    out[1 + n + 3] = (a.w + b.w + c.w + d.w) * sc.w;
}

// ---------------------------------------------------------------------------
extern "C" void kernel_launch(void* const* d_in, const int* in_sizes, int n_in,
                              void* d_out, int out_size)
{
    const float* state = (const float*)d_in[0];
    const float* xmax  = (const float*)d_in[1];
    const float* xmin  = (const float*)d_in[2];
    const float* W0    = (const float*)d_in[3];
    const float* b0    = (const float*)d_in[4];
    const float* W1    = (const float*)d_in[5];
    const float* b1    = (const float*)d_in[6];
    const float* W2    = (const float*)d_in[7];
    const float* b2    = (const float*)d_in[8];
    const float* W3    = (const float*)d_in[9];
    const float* b3    = (const float*)d_in[10];
    const float* Wout  = (const float*)d_in[11];
    const float* bout  = (const float*)d_in[12];
    float* out = (float*)d_out;

    k_norm<<<N_STATE / 4 / 256, 256>>>(state, xmax, xmin);
    dim3 gridA(SEG, H / RPB);
    k_fwd_matvec<<<gridA, 256>>>(W0);
    k_core<<<1, 512>>>(b0, W1, b1, W2, b2, W3, b3, Wout, bout, out);
    dim3 gridC(N_STATE / 2 / 256, JSPLIT);
    k_jv_part<<<gridC, 256>>>(W0);
    k_combine<<<N_STATE / 4 / 256, 256>>>(out);
}

// round 9
// speedup vs baseline: 2.2796x; 1.9445x over previous
#include <cuda_runtime.h>

#define N_STATE 131072
#define H 128
#define SEG 64          // n-segments in kernel A
#define RPB 4           // rows per block in kernel A

// Scratch (device globals — no allocation allowed)
__device__ float g_xnorm[N_STATE];
__device__ float g_scale[N_STATE];
__device__ float g_ypart[SEG * H];
__device__ float g_r[H];

// ---------------------------------------------------------------------------
// Kernel N: x_norm[n] = (2 s - mx - mn) / (mx - mn);  scale[n] = 2/(mx - mn)
// ---------------------------------------------------------------------------
__global__ __launch_bounds__(256)
void k_norm(const float* __restrict__ state,
            const float* __restrict__ xmax,
            const float* __restrict__ xmin)
{
    const int i = blockIdx.x * blockDim.x + threadIdx.x;   // float4 index
    float4 s  = ((const float4*)state)[i];
    float4 mx = ((const float4*)xmax)[i];
    float4 mn = ((const float4*)xmin)[i];
    float4 inv, xn, sc;
    inv.x = 1.0f / (mx.x - mn.x);
    inv.y = 1.0f / (mx.y - mn.y);
    inv.z = 1.0f / (mx.z - mn.z);
    inv.w = 1.0f / (mx.w - mn.w);
    xn.x = (2.0f * s.x - mx.x - mn.x) * inv.x;
    xn.y = (2.0f * s.y - mx.y - mn.y) * inv.y;
    xn.z = (2.0f * s.z - mx.z - mn.z) * inv.z;
    xn.w = (2.0f * s.w - mx.w - mn.w) * inv.w;
    sc.x = 2.0f * inv.x;  sc.y = 2.0f * inv.y;
    sc.z = 2.0f * inv.z;  sc.w = 2.0f * inv.w;
    ((float4*)g_xnorm)[i] = xn;
    ((float4*)g_scale)[i] = sc;
}

// ---------------------------------------------------------------------------
// Kernel A: partial y. grid (SEG=64, 32 rowgroups) = 2048 blocks x 256 thr.
// Each block: RPB=4 rows x 2048 columns; 2 unrolled iterations.
// ---------------------------------------------------------------------------
__global__ __launch_bounds__(256)
void k_fwd_matvec(const float* __restrict__ W0)
{
    const int seg = blockIdx.x;
    const int row0 = blockIdx.y * RPB;
    const int chunk4 = (N_STATE / SEG) / 4;                // 512 float4s

    const float4* __restrict__ xn = (const float4*)g_xnorm + (size_t)seg * chunk4;
    const float4* __restrict__ w0 = (const float4*)(W0 + (size_t)row0 * N_STATE) + (size_t)seg * chunk4;
    const size_t rstride4 = N_STATE / 4;

    float acc[RPB];
    #pragma unroll
    for (int r = 0; r < RPB; r++) acc[r] = 0.0f;

    #pragma unroll
    for (int it = 0; it < (N_STATE / SEG) / 4 / 256; it++) {   // 2 its
        const int i = it * 256 + threadIdx.x;
        float4 x = xn[i];
        #pragma unroll
        for (int r = 0; r < RPB; r++) {
            float4 wv = w0[(size_t)r * rstride4 + i];
            acc[r] += wv.x * x.x + wv.y * x.y + wv.z * x.z + wv.w * x.w;
        }
    }

    __shared__ float red[8][RPB];
    const int lane = threadIdx.x & 31, warp = threadIdx.x >> 5;
    #pragma unroll
    for (int r = 0; r < RPB; r++) {
        float v = acc[r];
        #pragma unroll
        for (int o = 16; o > 0; o >>= 1)
            v += __shfl_down_sync(0xffffffffu, v, o);
        if (lane == 0) red[warp][r] = v;
    }
    __syncthreads();
    if (threadIdx.x < RPB) {
        float v = 0.0f;
        #pragma unroll
        for (int w = 0; w < 8; w++) v += red[w][threadIdx.x];
        g_ypart[seg * H + row0 + threadIdx.x] = v;
    }
}

// ---------------------------------------------------------------------------
// Kernel B: core, 128 threads.
// Forward matvecs: warp-cooperative — warp w computes outputs w*32+jj via ONE
// coalesced float4 row load per output + butterfly shfl reduce (high MLP).
// Backward matvecs: thread-per-output column walk (naturally coalesced,
// weights L1-hot after the forward pass).
// ---------------------------------------------------------------------------
__global__ __launch_bounds__(128, 1)
void k_core(const float* __restrict__ b0,
            const float* __restrict__ W1, const float* __restrict__ b1,
            const float* __restrict__ W2, const float* __restrict__ b2,
            const float* __restrict__ W3, const float* __restrict__ b3,
            const float* __restrict__ Wout, const float* __restrict__ bout,
            float* __restrict__ out)
{
    __shared__ float v[H];
    __shared__ float tv[H];
    __shared__ float d0[H], d1[H], d2[H];

    const int tid = threadIdx.x;
    const int lane = tid & 31, warp = tid >> 5;

    // y[tid] = sum of segment partials (coalesced)
    float y = 0.0f;
    #pragma unroll
    for (int s = 0; s < SEG; s++) y += g_ypart[s * H + tid];

    float V = tanhf(y + b0[tid]);
    d0[tid] = 1.0f - V * V;
    v[tid] = V;
    __syncthreads();

    // ---- forward layer helper (warp-cooperative matvec) ----
    // After this block, thread tid holds output tid of W @ v in 'vn'.
    #define FWD_MATVEC(Wm, vn)                                                 \
    {                                                                          \
        float4 vv = ((const float4*)v)[lane];                                  \
        _Pragma("unroll")                                                      \
        for (int jj = 0; jj < 32; jj++) {                                      \
            const int j = warp * 32 + jj;                                      \
            float4 wv = ((const float4*)(Wm + j * H))[lane];                   \
            float p = wv.x * vv.x + wv.y * vv.y + wv.z * vv.z + wv.w * vv.w;   \
            _Pragma("unroll")                                                  \
            for (int o = 16; o > 0; o >>= 1)                                   \
                p += __shfl_xor_sync(0xffffffffu, p, o);                       \
            if (lane == jj) vn = p;                                            \
        }                                                                      \
    }

    // layer 0: W1 + tanh
    float vn = 0.0f;
    FWD_MATVEC(W1, vn);
    V = tanhf(vn + b1[tid]);
    d1[tid] = 1.0f - V * V;
    __syncthreads();
    v[tid] = V;
    __syncthreads();

    // layer 1: W2 + tanh
    FWD_MATVEC(W2, vn);
    V = tanhf(vn + b2[tid]);
    d2[tid] = 1.0f - V * V;
    __syncthreads();
    v[tid] = V;
    __syncthreads();

    // layer 2: W3 (no activation)
    FWD_MATVEC(W3, vn);
    V = vn + b3[tid];
    __syncthreads();
    v[tid] = V;
    __syncthreads();

    // output scalar: warp 0, 4 elements per lane
    if (tid < 32) {
        float p = 0.0f;
        #pragma unroll
        for (int s = 0; s < 4; s++)
            p += Wout[tid + 32 * s] * v[tid + 32 * s];
        #pragma unroll
        for (int o = 16; o > 0; o >>= 1)
            p += __shfl_down_sync(0xffffffffu, p, o);
        if (tid == 0) out[0] = p + bout[0];
    }

    // backward: r^T = Wout W3 D2 W2 D1 W1 D0  (coalesced column walks)
    tv[tid] = Wout[tid];
    __syncthreads();

    {
        float a = 0.0f;
        #pragma unroll 16
        for (int i = 0; i < H; i++) a += tv[i] * W3[i * H + tid];
        a *= d2[tid];
        __syncthreads();
        tv[tid] = a;
        __syncthreads();
    }
    {
        float a = 0.0f;
        #pragma unroll 16
        for (int i = 0; i < H; i++) a += tv[i] * W2[i * H + tid];
        a *= d1[tid];
        __syncthreads();
        tv[tid] = a;
        __syncthreads();
    }
    {
        float a = 0.0f;
        #pragma unroll 16
        for (int i = 0; i < H; i++) a += tv[i] * W1[i * H + tid];
        g_r[tid] = a * d0[tid];
    }
    #undef FWD_MATVEC
}

// ---------------------------------------------------------------------------
// Kernel C: JV[n] = scale[n] * sum_i r[i] * W0[i, n]
// 256 blocks x 256 threads, float2 per thread (R3 measured-best single pass).
// ---------------------------------------------------------------------------
__global__ __launch_bounds__(256, 4)
void k_jv(const float* __restrict__ W0, float* __restrict__ out)
{
    __shared__ float r[H];
    if (threadIdx.x < H) r[threadIdx.x] = g_r[threadIdx.x];
    __syncthreads();

    const int n2 = blockIdx.x * blockDim.x + threadIdx.x;   // float2 index
    const float2* __restrict__ w = (const float2*)W0;
    const size_t stride2 = N_STATE / 2;

    float ax = 0.0f, ay = 0.0f;
    #pragma unroll 16
    for (int i = 0; i < H; i++) {
        float2 wv = w[(size_t)i * stride2 + n2];
        float ri = r[i];
        ax += ri * wv.x;
        ay += ri * wv.y;
    }

    float2 sc = ((const float2*)g_scale)[n2];
    const int n = n2 * 2;
    out[1 + n + 0] = ax * sc.x;
    out[1 + n + 1] = ay * sc.y;
}

// ---------------------------------------------------------------------------
extern "C" void kernel_launch(void* const* d_in, const int* in_sizes, int n_in,
                              void* d_out, int out_size)
{
    const float* state = (const float*)d_in[0];
    const float* xmax  = (const float*)d_in[1];
    const float* xmin  = (const float*)d_in[2];
    const float* W0    = (const float*)d_in[3];
    const float* b0    = (const float*)d_in[4];
    const float* W1    = (const float*)d_in[5];
    const float* b1    = (const float*)d_in[6];
    const float* W2    = (const float*)d_in[7];
    const float* b2    = (const float*)d_in[8];
    const float* W3    = (const float*)d_in[9];
    const float* b3    = (const float*)d_in[10];
    const float* Wout  = (const float*)d_in[11];
    const float* bout  = (const float*)d_in[12];
    float* out = (float*)d_out;

    k_norm<<<N_STATE / 4 / 256, 256>>>(state, xmax, xmin);
    dim3 gridA(SEG, H / RPB);
    k_fwd_matvec<<<gridA, 256>>>(W0);
    k_core<<<1, H>>>(b0, W1, b1, W2, b2, W3, b3, Wout, bout, out);
    k_jv<<<(N_STATE / 2) / 256, 256>>>(W0, out);
}